// round 1
// baseline (speedup 1.0000x reference)
#include <cuda_runtime.h>
#include <math.h>

#define BSZ 4096
#define CSZ 16000
#define C4  (CSZ/4)
#define NM1 ((float)(CSZ-1))
#define LOG2E 1.4426950408889634f

// ---------------- scratch (device globals; no allocation allowed) ----------
__device__ float  g_rowmax[2][BSZ];
__device__ float  g_rowsum[2][BSZ];
__device__ int    g_cnt[2][BSZ][10];
__device__ int    g_amax[2][BSZ];
__device__ float4 g_stats[BSZ];          // {-log2(Zs), -log2(Zt), max_s, max_t}
__device__ float  g_s1[CSZ], g_s2[CSZ], g_t1[CSZ], g_t2[CSZ], g_st[CSZ];

static __device__ __forceinline__ float ex2f(float x) {
    float y;
    asm("ex2.approx.f32 %0, %1;" : "=f"(y) : "f"(x));
    return y;
}

// ---------------- kernel 0: init accumulators --------------------------------
__global__ void k_init() {
    int i = blockIdx.x * blockDim.x + threadIdx.x;
    if (i < CSZ) {
        g_s1[i] = 0.f; g_s2[i] = 0.f; g_t1[i] = 0.f; g_t2[i] = 0.f; g_st[i] = 0.f;
    }
    if (i < 2 * BSZ) {
        (&g_amax[0][0])[i] = 0x7FFFFFFF;
    }
}

// ---------------- kernel 1: row pass (max, sum-exp, 10 rank counts) ----------
__global__ void __launch_bounds__(256) k_rowstats(const float* __restrict__ zs,
                                                  const float* __restrict__ zt) {
    const int b = blockIdx.x;
    const int t = blockIdx.y;
    const float* row = (t == 0 ? zs : zt) + (size_t)b * CSZ;
    const float4* row4 = (const float4*)row;

    float u[10];
#pragma unroll
    for (int j = 0; j < 10; j++) u[j] = row[j];   // broadcast loads (L1 hit)

    float mx = -1e30f, sm = 0.f;
    int cnt[10];
#pragma unroll
    for (int j = 0; j < 10; j++) cnt[j] = 0;

    for (int i = threadIdx.x; i < C4; i += 256) {
        float4 v = row4[i];
#pragma unroll
        for (int k = 0; k < 4; k++) {
            float x = (k == 0 ? v.x : k == 1 ? v.y : k == 2 ? v.z : v.w);
            mx = fmaxf(mx, x);
            sm += ex2f(x * LOG2E);                 // sum exp(z) (no overflow: |z|<~6)
#pragma unroll
            for (int j = 0; j < 10; j++) cnt[j] += (x < u[j]);
        }
    }

    // warp reduce
    const unsigned FULL = 0xffffffffu;
#pragma unroll
    for (int o = 16; o; o >>= 1) {
        mx = fmaxf(mx, __shfl_xor_sync(FULL, mx, o));
        sm += __shfl_xor_sync(FULL, sm, o);
#pragma unroll
        for (int j = 0; j < 10; j++) cnt[j] += __shfl_xor_sync(FULL, cnt[j], o);
    }

    __shared__ float smx[8], ssm[8];
    __shared__ int scnt[8][10];
    int w = threadIdx.x >> 5, lane = threadIdx.x & 31;
    if (lane == 0) {
        smx[w] = mx; ssm[w] = sm;
#pragma unroll
        for (int j = 0; j < 10; j++) scnt[w][j] = cnt[j];
    }
    __syncthreads();
    if (threadIdx.x == 0) {
#pragma unroll
        for (int ww = 1; ww < 8; ww++) {
            mx = fmaxf(mx, smx[ww]);
            sm += ssm[ww];
#pragma unroll
            for (int j = 0; j < 10; j++) cnt[j] += scnt[ww][j];
        }
        g_rowmax[t][b] = mx;
        g_rowsum[t][b] = sm;
#pragma unroll
        for (int j = 0; j < 10; j++) g_cnt[t][b][j] = cnt[j];
    }
}

// ---------------- kernel 2: per-row softmax constants ------------------------
__global__ void k_prep() {
    int b = blockIdx.x * blockDim.x + threadIdx.x;
    if (b < BSZ) {
        g_stats[b] = make_float4(-log2f(g_rowsum[0][b]), -log2f(g_rowsum[1][b]),
                                 g_rowmax[0][b], g_rowmax[1][b]);
    }
}

// ---------------- kernel 3: column pass (intra stats + argmax) ---------------
__global__ void __launch_bounds__(256) k_colstats(const float* __restrict__ zs,
                                                  const float* __restrict__ zt) {
    const int c = blockIdx.x * 1024 + threadIdx.x * 4;
    if (c >= CSZ) return;
    const int r0 = blockIdx.y * 128, r1 = r0 + 128;

    float a1[4] = {0, 0, 0, 0}, a2[4] = {0, 0, 0, 0};
    float b1[4] = {0, 0, 0, 0}, b2[4] = {0, 0, 0, 0};
    float ab[4] = {0, 0, 0, 0};

    for (int r = r0; r < r1; r++) {
        float4 stv = g_stats[r];                                     // uniform
        float4 xs = *(const float4*)(zs + (size_t)r * CSZ + c);
        float4 xt = *(const float4*)(zt + (size_t)r * CSZ + c);
#pragma unroll
        for (int k = 0; k < 4; k++) {
            float xsk = (k == 0 ? xs.x : k == 1 ? xs.y : k == 2 ? xs.z : xs.w);
            float xtk = (k == 0 ? xt.x : k == 1 ? xt.y : k == 2 ? xt.z : xt.w);
            float ys = ex2f(fmaf(xsk, LOG2E, stv.x));                // y = e^z / Z
            float yt = ex2f(fmaf(xtk, LOG2E, stv.y));
            a1[k] += ys; a2[k] = fmaf(ys, ys, a2[k]);
            b1[k] += yt; b2[k] = fmaf(yt, yt, b2[k]);
            ab[k] = fmaf(ys, yt, ab[k]);
            if (xsk == stv.z) atomicMin(&g_amax[0][r], c + k);       // first argmax
            if (xtk == stv.w) atomicMin(&g_amax[1][r], c + k);
        }
    }
#pragma unroll
    for (int k = 0; k < 4; k++) {
        atomicAdd(&g_s1[c + k], a1[k]);
        atomicAdd(&g_s2[c + k], a2[k]);
        atomicAdd(&g_t1[c + k], b1[k]);
        atomicAdd(&g_t2[c + k], b2[k]);
        atomicAdd(&g_st[c + k], ab[k]);
    }
}

// ---------------- kernel 4: finalize -----------------------------------------
__global__ void __launch_bounds__(256) k_final(float* __restrict__ out) {
    const int tid = threadIdx.x;
    double intra = 0.0, sp = 0.0, eq = 0.0;

    // intra-class pearson per column
    const float invB = 1.f / (float)BSZ;
    for (int c = tid; c < CSZ; c += 256) {
        float s1 = g_s1[c], s2 = g_s2[c], t1 = g_t1[c], t2 = g_t2[c], st = g_st[c];
        float num = st - s1 * t1 * invB;
        float vs = s2 - s1 * s1 * invB;
        float vt = t2 - t1 * t1 * invB;
        float den = sqrtf(fmaxf(vs, 0.f)) * sqrtf(fmaxf(vt, 0.f)) + 1e-8f;
        intra += (double)(num / den);
    }

    // inter-class spearman-variant per row (sparse closed form)
    for (int b = tid; b < BSZ; b += 256) {
        int js = g_amax[0][b], jt = g_amax[1][b];
        eq += (js == jt) ? 1.0 : 0.0;

        int ms[10], mt[10];
        bool ks[10], kt[10];
        float Ds = 0.f, Qs = 0.f, Dt = 0.f, Qt = 0.f;
#pragma unroll
        for (int i = 0; i < 10; i++) {
            int p = g_cnt[0][b][i];
            ks[i] = (p != js);
            ms[i] = p - (p > js ? 1 : 0);
            float v = (float)(10 - i);
            if (ks[i]) { Ds += v; Qs += v * v; }
            p = g_cnt[1][b][i];
            kt[i] = (p != jt);
            mt[i] = p - (p > jt ? 1 : 0);
            if (kt[i]) { Dt += v; Qt += v * v; }
        }
        float X = 0.f;
#pragma unroll
        for (int i = 0; i < 10; i++) {
#pragma unroll
            for (int k2 = 0; k2 < 10; k2++) {
                if (ks[i] && kt[k2] && (ms[i] == mt[k2]))
                    X += (float)(10 - i) * (float)(10 - k2);
            }
        }
        float num = X - Ds * Dt / NM1;
        float den = sqrtf(fmaxf(Qs - Ds * Ds / NM1, 0.f)) *
                    sqrtf(fmaxf(Qt - Dt * Dt / NM1, 0.f)) + 1e-8f;
        sp += (double)(num / den);
    }

    __shared__ double sh0[256], sh1[256], sh2[256];
    sh0[tid] = intra; sh1[tid] = sp; sh2[tid] = eq;
    __syncthreads();
    for (int s = 128; s; s >>= 1) {
        if (tid < s) {
            sh0[tid] += sh0[tid + s];
            sh1[tid] += sh1[tid + s];
            sh2[tid] += sh2[tid + s];
        }
        __syncthreads();
    }
    if (tid == 0) {
        double inter_loss = 1.0 - (sh2[0] / (double)BSZ + sh1[0] / (double)BSZ);
        double intra_loss = 1.0 - sh0[0] / (double)CSZ;
        out[0] = (float)(inter_loss + intra_loss);
    }
}

// ---------------- launch ------------------------------------------------------
extern "C" void kernel_launch(void* const* d_in, const int* in_sizes, int n_in,
                              void* d_out, int out_size) {
    const float* zs = (const float*)d_in[0];
    const float* zt = (const float*)d_in[1];

    k_init<<<(CSZ + 255) / 256, 256>>>();

    dim3 g1(BSZ, 2);
    k_rowstats<<<g1, 256>>>(zs, zt);

    k_prep<<<(BSZ + 255) / 256, 256>>>();

    dim3 g2(16, 32);
    k_colstats<<<g2, 256>>>(zs, zt);

    k_final<<<1, 256>>>((float*)d_out);
}

// round 2
// speedup vs baseline: 1.2568x; 1.2568x over previous
#include <cuda_runtime.h>
#include <math.h>

#define BSZ 4096
#define CSZ 16000
#define C4  4000
#define NM1 15999.0f
#define LOG2E 1.4426950408889634f

// ---------------- scratch (device globals) ----------------------------------
__device__ float  g_rowmax[2][BSZ];
__device__ float  g_rowsum[2][BSZ];
__device__ int    g_cnt[2][BSZ][10];
__device__ int    g_amax[2][BSZ];
__device__ float4 g_stats[BSZ];          // {-log2(Zs), -log2(Zt), max_s, max_t}
__device__ float  g_s1[CSZ], g_s2[CSZ], g_t1[CSZ], g_t2[CSZ], g_st[CSZ];
__device__ double g_pintra[64], g_psp[16], g_peq[16];

static __device__ __forceinline__ float ex2f(float x) {
    float y;
    asm("ex2.approx.f32 %0, %1;" : "=f"(y) : "f"(x));
    return y;
}

// ---------------- kernel 0: init --------------------------------------------
__global__ void k_init() {
    int i = blockIdx.x * blockDim.x + threadIdx.x;
    if (i < CSZ) {
        g_s1[i] = 0.f; g_s2[i] = 0.f; g_t1[i] = 0.f; g_t2[i] = 0.f; g_st[i] = 0.f;
    }
    if (i < 2 * BSZ) (&g_amax[0][0])[i] = 0x7FFFFFFF;
}

// ---------------- kernel 1: row pass (max, sum-exp, 10 rank counts) ----------
__global__ void __launch_bounds__(256) k_rowstats(const float* __restrict__ zs,
                                                  const float* __restrict__ zt) {
    const int b = blockIdx.x;
    const int t = blockIdx.y;
    const float* row = (t == 0 ? zs : zt) + (size_t)b * CSZ;
    const float4* row4 = (const float4*)row;

    float u[10];
#pragma unroll
    for (int j = 0; j < 10; j++) u[j] = row[j];   // broadcast, L1 hit

    float mx = -1e30f;
    float sm0 = 0.f, sm1 = 0.f, sm2 = 0.f, sm3 = 0.f;
    int cnt[10];
#pragma unroll
    for (int j = 0; j < 10; j++) cnt[j] = 0;

#pragma unroll 4
    for (int i = threadIdx.x; i < C4; i += 256) {
        float4 v = __ldcs(row4 + i);
        sm0 += ex2f(v.x * LOG2E);
        sm1 += ex2f(v.y * LOG2E);
        sm2 += ex2f(v.z * LOG2E);
        sm3 += ex2f(v.w * LOG2E);
        mx = fmaxf(mx, fmaxf(fmaxf(v.x, v.y), fmaxf(v.z, v.w)));
#pragma unroll
        for (int j = 0; j < 10; j++)
            cnt[j] += (int)(v.x < u[j]) + (int)(v.y < u[j]) +
                      (int)(v.z < u[j]) + (int)(v.w < u[j]);
    }
    float sm = (sm0 + sm1) + (sm2 + sm3);

    const unsigned FULL = 0xffffffffu;
#pragma unroll
    for (int o = 16; o; o >>= 1) {
        mx = fmaxf(mx, __shfl_xor_sync(FULL, mx, o));
        sm += __shfl_xor_sync(FULL, sm, o);
    }
#pragma unroll
    for (int j = 0; j < 10; j++) cnt[j] = __reduce_add_sync(FULL, cnt[j]);

    __shared__ float smx[8], ssm[8];
    __shared__ int scnt[8][10];
    int w = threadIdx.x >> 5, lane = threadIdx.x & 31;
    if (lane == 0) {
        smx[w] = mx; ssm[w] = sm;
#pragma unroll
        for (int j = 0; j < 10; j++) scnt[w][j] = cnt[j];
    }
    __syncthreads();
    if (threadIdx.x == 0) {
#pragma unroll
        for (int ww = 1; ww < 8; ww++) {
            mx = fmaxf(mx, smx[ww]);
            sm += ssm[ww];
#pragma unroll
            for (int j = 0; j < 10; j++) cnt[j] += scnt[ww][j];
        }
        g_rowmax[t][b] = mx;
        g_rowsum[t][b] = sm;
#pragma unroll
        for (int j = 0; j < 10; j++) g_cnt[t][b][j] = cnt[j];
    }
}

// ---------------- kernel 2: per-row softmax constants ------------------------
__global__ void k_prep() {
    int b = blockIdx.x * blockDim.x + threadIdx.x;
    if (b < BSZ) {
        g_stats[b] = make_float4(-log2f(g_rowsum[0][b]), -log2f(g_rowsum[1][b]),
                                 g_rowmax[0][b], g_rowmax[1][b]);
    }
}

// ---------------- kernel 3: column pass (intra stats + argmax) ---------------
// grid (16, 128): 1024 cols per x-block, 32 rows per y-block.
__global__ void __launch_bounds__(256) k_colstats(const float* __restrict__ zs,
                                                  const float* __restrict__ zt) {
    const int c = blockIdx.x * 1024 + threadIdx.x * 4;
    if (c >= CSZ) return;
    const int r0 = blockIdx.y * 32;

    float a1[4] = {0, 0, 0, 0}, a2[4] = {0, 0, 0, 0};
    float b1[4] = {0, 0, 0, 0}, b2[4] = {0, 0, 0, 0};
    float ab[4] = {0, 0, 0, 0};

#pragma unroll 2
    for (int rr = 0; rr < 32; rr++) {
        const int r = r0 + rr;
        const float4 stv = g_stats[r];                               // uniform
        const float4 xs = __ldcs((const float4*)(zs + (size_t)r * CSZ + c));
        const float4 xt = __ldcs((const float4*)(zt + (size_t)r * CSZ + c));
#pragma unroll
        for (int k = 0; k < 4; k++) {
            float xsk = (k == 0 ? xs.x : k == 1 ? xs.y : k == 2 ? xs.z : xs.w);
            float xtk = (k == 0 ? xt.x : k == 1 ? xt.y : k == 2 ? xt.z : xt.w);
            float ys = ex2f(fmaf(xsk, LOG2E, stv.x));
            float yt = ex2f(fmaf(xtk, LOG2E, stv.y));
            a1[k] += ys; a2[k] = fmaf(ys, ys, a2[k]);
            b1[k] += yt; b2[k] = fmaf(yt, yt, b2[k]);
            ab[k] = fmaf(ys, yt, ab[k]);
            if (xsk == stv.z) atomicMin(&g_amax[0][r], c + k);
            if (xtk == stv.w) atomicMin(&g_amax[1][r], c + k);
        }
    }
#pragma unroll
    for (int k = 0; k < 4; k++) {
        atomicAdd(&g_s1[c + k], a1[k]);
        atomicAdd(&g_s2[c + k], a2[k]);
        atomicAdd(&g_t1[c + k], b1[k]);
        atomicAdd(&g_t2[c + k], b2[k]);
        atomicAdd(&g_st[c + k], ab[k]);
    }
}

// ---------------- kernel 4: parallel partial reductions ----------------------
// blocks 0..63  : intra pearson over 250 columns each
// blocks 64..79 : inter spearman/eq over 256 rows each (one row per thread)
__global__ void __launch_bounds__(256) k_partial() {
    const int bid = blockIdx.x;
    const int tid = threadIdx.x;
    __shared__ double sh0[256], sh1[256];

    if (bid < 64) {
        double intra = 0.0;
        const float invB = 1.f / (float)BSZ;
        int c = bid * 250 + tid;
        if (tid < 250) {
            float s1 = g_s1[c], s2 = g_s2[c], t1 = g_t1[c], t2 = g_t2[c], st = g_st[c];
            float num = st - s1 * t1 * invB;
            float vs = s2 - s1 * s1 * invB;
            float vt = t2 - t1 * t1 * invB;
            float den = sqrtf(fmaxf(vs, 0.f)) * sqrtf(fmaxf(vt, 0.f)) + 1e-8f;
            intra = (double)(num / den);
        }
        sh0[tid] = intra; sh1[tid] = 0.0;
        __syncthreads();
        for (int s = 128; s; s >>= 1) {
            if (tid < s) sh0[tid] += sh0[tid + s];
            __syncthreads();
        }
        if (tid == 0) g_pintra[bid] = sh0[0];
    } else {
        const int b = (bid - 64) * 256 + tid;
        const int js = g_amax[0][b], jt = g_amax[1][b];
        double eq = (js == jt) ? 1.0 : 0.0;

        int ms[10], mt[10];
        bool ks[10], kt[10];
        float Ds = 0.f, Qs = 0.f, Dt = 0.f, Qt = 0.f;
#pragma unroll
        for (int i = 0; i < 10; i++) {
            int p = g_cnt[0][b][i];
            ks[i] = (p != js);
            ms[i] = p - (p > js ? 1 : 0);
            float v = (float)(10 - i);
            if (ks[i]) { Ds += v; Qs += v * v; }
            p = g_cnt[1][b][i];
            kt[i] = (p != jt);
            mt[i] = p - (p > jt ? 1 : 0);
            if (kt[i]) { Dt += v; Qt += v * v; }
        }
        float X = 0.f;
#pragma unroll
        for (int i = 0; i < 10; i++) {
#pragma unroll
            for (int k2 = 0; k2 < 10; k2++) {
                if (ks[i] && kt[k2] && (ms[i] == mt[k2]))
                    X += (float)(10 - i) * (float)(10 - k2);
            }
        }
        float num = X - Ds * Dt / NM1;
        float den = sqrtf(fmaxf(Qs - Ds * Ds / NM1, 0.f)) *
                    sqrtf(fmaxf(Qt - Dt * Dt / NM1, 0.f)) + 1e-8f;
        double sp = (double)(num / den);

        sh0[tid] = sp; sh1[tid] = eq;
        __syncthreads();
        for (int s = 128; s; s >>= 1) {
            if (tid < s) { sh0[tid] += sh0[tid + s]; sh1[tid] += sh1[tid + s]; }
            __syncthreads();
        }
        if (tid == 0) { g_psp[bid - 64] = sh0[0]; g_peq[bid - 64] = sh1[0]; }
    }
}

// ---------------- kernel 5: combine ------------------------------------------
__global__ void __launch_bounds__(128) k_combine(float* __restrict__ out) {
    const int tid = threadIdx.x;
    __shared__ double sh0[128], sh1[128], sh2[128];
    double a = 0.0, b = 0.0, c = 0.0;
    if (tid < 64) a = g_pintra[tid];
    if (tid < 16) { b = g_psp[tid]; c = g_peq[tid]; }
    sh0[tid] = a; sh1[tid] = b; sh2[tid] = c;
    __syncthreads();
    for (int s = 64; s; s >>= 1) {
        if (tid < s) {
            sh0[tid] += sh0[tid + s];
            sh1[tid] += sh1[tid + s];
            sh2[tid] += sh2[tid + s];
        }
        __syncthreads();
    }
    if (tid == 0) {
        double inter_loss = 1.0 - (sh2[0] / (double)BSZ + sh1[0] / (double)BSZ);
        double intra_loss = 1.0 - sh0[0] / (double)CSZ;
        out[0] = (float)(inter_loss + intra_loss);
    }
}

// ---------------- launch ------------------------------------------------------
extern "C" void kernel_launch(void* const* d_in, const int* in_sizes, int n_in,
                              void* d_out, int out_size) {
    const float* zs = (const float*)d_in[0];
    const float* zt = (const float*)d_in[1];

    k_init<<<(CSZ + 255) / 256, 256>>>();

    dim3 g1(BSZ, 2);
    k_rowstats<<<g1, 256>>>(zs, zt);

    k_prep<<<(BSZ + 255) / 256, 256>>>();

    dim3 g2(16, 128);
    k_colstats<<<g2, 256>>>(zs, zt);

    k_partial<<<80, 256>>>();
    k_combine<<<1, 128>>>((float*)d_out);
}